// round 6
// baseline (speedup 1.0000x reference)
#include <cuda_runtime.h>
#include <float.h>

#define NG 5
#define NB 131072
#define NK 512
#define ND 64
#define CTA 256
#define RB 128                       // rows per CTA
#define KT 64                        // codewords per k-tile
#define NTILES (NK / KT)             // 8
#define XBLK (NB / RB)               // 1024
#define NCTAS (NG * XBLK)            // 5120
#define XPAD 130                     // u64 row-stride for x_bcast[d][row]
#define CPAD 34                      // u64 pair-stride for cb tile [d][pair]

typedef unsigned long long u64;

__device__ float g_part[NCTAS];
__device__ unsigned int g_done = 0;

__device__ __forceinline__ u64 ffma2(u64 a, u64 b, u64 c) {
    u64 d;
    asm("fma.rn.f32x2 %0, %1, %2, %3;" : "=l"(d) : "l"(a), "l"(b), "l"(c));
    return d;
}
__device__ __forceinline__ u64 bcast2(float f) {
    u64 r;
    asm("mov.b64 %0, {%1, %1};" : "=l"(r) : "f"(f));
    return r;
}
__device__ __forceinline__ void unpack2(u64 v, float& lo, float& hi) {
    asm("mov.b64 {%0, %1}, %2;" : "=f"(lo), "=f"(hi) : "l"(v));
}
__device__ __forceinline__ float lo32(u64 v) {
    float a, b; unpack2(v, a, b); return a;
}

__global__ __launch_bounds__(CTA, 2) void vq_kernel(
    const float* __restrict__ feat,   // [G,B,D]
    const float* __restrict__ cb,     // [G,K,D]
    float* __restrict__ out_q,        // [G,B,D]
    float* __restrict__ out_loss,     // [G+1]
    float* __restrict__ out_idx,      // [G,B] as float
    int write_q, int write_loss, int write_idx)
{
    extern __shared__ u64 sh[];
    u64*   sh_x   = sh;                                  // [64][XPAD] u64 bcast pairs
    u64*   sh_c   = sh_x + (size_t)ND * XPAD;            // [64][CPAD] u64 cw pairs
    float* sh_esq = (float*)(sh_c + (size_t)ND * CPAD);  // [512]
    float* sh_xsq = sh_esq + NK;                          // [128]
    float* sh_red = sh_xsq + RB;                          // [8]

    const int tid = threadIdx.x;
    const int tc = tid & 15;          // codeword-column 0..15
    const int tr = tid >> 4;          // row-group 0..15 (8 rows each)
    const int g = blockIdx.y;
    const int base_row = blockIdx.x * RB;

    const float* cbg = cb + (size_t)g * NK * ND;

    // ---- Stage features as broadcast u64 pairs: sh_x[d*XPAD + row] = (x,x) ----
    {
        const float4* xin = (const float4*)(feat + ((size_t)g * NB + base_row) * ND);
        #pragma unroll
        for (int it = 0; it < (RB * ND / 4) / CTA; it++) {
            int i = it * CTA + tid;
            float4 v = xin[i];
            int e = i * 4;
            int row = e >> 6, d = e & 63;
            u64* p = sh_x + (size_t)d * XPAD + row;
            p[0 * XPAD] = bcast2(v.x);
            p[1 * XPAD] = bcast2(v.y);
            p[2 * XPAD] = bcast2(v.z);
            p[3 * XPAD] = bcast2(v.w);
        }
    }

    // ---- e_sq for all 512 codewords (2 per thread, sequential-d fma chain) ----
    {
        #pragma unroll
        for (int s = 0; s < 2; s++) {
            int k = tid * 2 + s;
            const float4* cp = (const float4*)(cbg + (size_t)k * ND);
            float acc = 0.f;
            #pragma unroll
            for (int i = 0; i < 16; i++) {
                float4 v = cp[i];
                acc = fmaf(v.x, v.x, acc);
                acc = fmaf(v.y, v.y, acc);
                acc = fmaf(v.z, v.z, acc);
                acc = fmaf(v.w, v.w, acc);
            }
            sh_esq[k] = acc;
        }
    }
    __syncthreads();

    // ---- x_sq per row (sequential-d chain from staged x) ----
    if (tid < RB) {
        float acc = 0.f;
        const u64* xp = sh_x + tid;
        #pragma unroll
        for (int d = 0; d < ND; d++) {
            float v = lo32(xp[(size_t)d * XPAD]);
            acc = fmaf(v, v, acc);
        }
        sh_xsq[tid] = acc;
    }
    __syncthreads();

    float xsr[8];
    #pragma unroll
    for (int r = 0; r < 8; r++) xsr[r] = sh_xsq[8 * tr + r];

    float best[8];
    int bk[8];
    #pragma unroll
    for (int r = 0; r < 8; r++) { best[r] = FLT_MAX; bk[r] = 0; }

    // ---- K-tiles: stage 64 codewords pair-interleaved, accumulate, compare ----
    #pragma unroll 1
    for (int t = 0; t < NTILES; t++) {
        __syncthreads();   // previous tile fully consumed before overwrite
        {
            const float4* cin = (const float4*)(cbg + (size_t)t * KT * ND);
            float* cf = (float*)sh_c;
            #pragma unroll
            for (int it = 0; it < (KT * ND / 4) / CTA; it++) {
                int i = it * CTA + tid;
                float4 v = cin[i];
                int e = i * 4;
                int kk = e >> 6, d = e & 63;
                int pk = kk >> 1, ln = kk & 1;
                int fo = ((d * CPAD) + pk) * 2 + ln;
                cf[fo + 0 * CPAD * 2] = v.x;
                cf[fo + 1 * CPAD * 2] = v.y;
                cf[fo + 2 * CPAD * 2] = v.z;
                cf[fo + 3 * CPAD * 2] = v.w;
            }
        }
        __syncthreads();

        u64 a00 = 0, a01 = 0, a10 = 0, a11 = 0, a20 = 0, a21 = 0, a30 = 0, a31 = 0;
        u64 a40 = 0, a41 = 0, a50 = 0, a51 = 0, a60 = 0, a61 = 0, a70 = 0, a71 = 0;
        {
            const u64* cp = sh_c + 2 * tc;     // pairs 2tc, 2tc+1
            const u64* xp = sh_x + 8 * tr;     // rows 8tr..8tr+7
            #pragma unroll
            for (int d = 0; d < ND; d++) {
                ulonglong2 c01 = *(const ulonglong2*)(cp + (size_t)d * CPAD);
                ulonglong2 x01 = *(const ulonglong2*)(xp + (size_t)d * XPAD);
                ulonglong2 x23 = *(const ulonglong2*)(xp + (size_t)d * XPAD + 2);
                ulonglong2 x45 = *(const ulonglong2*)(xp + (size_t)d * XPAD + 4);
                ulonglong2 x67 = *(const ulonglong2*)(xp + (size_t)d * XPAD + 6);
                a00 = ffma2(x01.x, c01.x, a00); a01 = ffma2(x01.x, c01.y, a01);
                a10 = ffma2(x01.y, c01.x, a10); a11 = ffma2(x01.y, c01.y, a11);
                a20 = ffma2(x23.x, c01.x, a20); a21 = ffma2(x23.x, c01.y, a21);
                a30 = ffma2(x23.y, c01.x, a30); a31 = ffma2(x23.y, c01.y, a31);
                a40 = ffma2(x45.x, c01.x, a40); a41 = ffma2(x45.x, c01.y, a41);
                a50 = ffma2(x45.y, c01.x, a50); a51 = ffma2(x45.y, c01.y, a51);
                a60 = ffma2(x67.x, c01.x, a60); a61 = ffma2(x67.x, c01.y, a61);
                a70 = ffma2(x67.y, c01.x, a70); a71 = ffma2(x67.y, c01.y, a71);
            }
        }

        // distances for codewords kbase..kbase+3, ascending within thread
        const int kbase = t * KT + 4 * tc;
        const float e0 = sh_esq[kbase + 0];
        const float e1 = sh_esq[kbase + 1];
        const float e2 = sh_esq[kbase + 2];
        const float e3 = sh_esq[kbase + 3];
        #define TILE_EPI(r, A0, A1)                                            \
        {                                                                      \
            float cl, ch;                                                      \
            unpack2(A0, cl, ch);                                               \
            float d0 = (xsr[r] + e0) - 2.0f * cl;                              \
            float d1 = (xsr[r] + e1) - 2.0f * ch;                              \
            unpack2(A1, cl, ch);                                               \
            float d2 = (xsr[r] + e2) - 2.0f * cl;                              \
            float d3 = (xsr[r] + e3) - 2.0f * ch;                              \
            if (d0 < best[r]) { best[r] = d0; bk[r] = kbase + 0; }             \
            if (d1 < best[r]) { best[r] = d1; bk[r] = kbase + 1; }             \
            if (d2 < best[r]) { best[r] = d2; bk[r] = kbase + 2; }             \
            if (d3 < best[r]) { best[r] = d3; bk[r] = kbase + 3; }             \
        }
        TILE_EPI(0, a00, a01) TILE_EPI(1, a10, a11)
        TILE_EPI(2, a20, a21) TILE_EPI(3, a30, a31)
        TILE_EPI(4, a40, a41) TILE_EPI(5, a50, a51)
        TILE_EPI(6, a60, a61) TILE_EPI(7, a70, a71)
        #undef TILE_EPI
    }

    // ---- Cross-lane argmin over the 16 tc-columns (tie -> smaller k) ----
    #pragma unroll
    for (int r = 0; r < 8; r++) {
        #pragma unroll
        for (int m = 1; m < 16; m <<= 1) {
            float ob = __shfl_xor_sync(0xFFFFFFFFu, best[r], m);
            int   ok = __shfl_xor_sync(0xFFFFFFFFu, bk[r], m);
            if (ob < best[r] || (ob == best[r] && ok < bk[r])) {
                best[r] = ob; bk[r] = ok;
            }
        }
    }

    // ---- Outputs: quantized_st = x + (q - x), indices, loss partials ----
    float lsum = 0.f;
    #pragma unroll
    for (int r = 0; r < 8; r++) {
        const int row = 8 * tr + r;
        const int k = bk[r];
        float4 q = *(const float4*)(cbg + (size_t)k * ND + 4 * tc);
        float x0 = lo32(sh_x[(size_t)(4 * tc + 0) * XPAD + row]);
        float x1 = lo32(sh_x[(size_t)(4 * tc + 1) * XPAD + row]);
        float x2 = lo32(sh_x[(size_t)(4 * tc + 2) * XPAD + row]);
        float x3 = lo32(sh_x[(size_t)(4 * tc + 3) * XPAD + row]);
        float dx0 = q.x - x0, dx1 = q.y - x1, dx2 = q.z - x2, dx3 = q.w - x3;
        lsum = fmaf(dx0, dx0, lsum);
        lsum = fmaf(dx1, dx1, lsum);
        lsum = fmaf(dx2, dx2, lsum);
        lsum = fmaf(dx3, dx3, lsum);
        if (write_q) {
            float4 o = make_float4(x0 + dx0, x1 + dx1, x2 + dx2, x3 + dx3);
            *(float4*)(out_q + ((size_t)g * NB + base_row + row) * ND + 4 * tc) = o;
        }
        if (write_idx && tc == 0)
            out_idx[(size_t)g * NB + base_row + row] = (float)k;
    }

    // ---- Loss: warp shuffle -> shared -> per-CTA partial; last CTA finalizes ----
    #pragma unroll
    for (int off = 16; off > 0; off >>= 1)
        lsum += __shfl_xor_sync(0xFFFFFFFFu, lsum, off);
    __syncthreads();               // sh_x reads done before reusing nothing; safe point
    if ((tid & 31) == 0) sh_red[tid >> 5] = lsum;
    __syncthreads();
    if (tid == 0) {
        double s = 0.0;
        #pragma unroll
        for (int w = 0; w < CTA / 32; w++) s += (double)sh_red[w];
        g_part[g * XBLK + blockIdx.x] = (float)s;
        __threadfence();
        unsigned int t = atomicAdd(&g_done, 1u);
        if (t == NCTAS - 1) {
            __threadfence();
            if (write_loss) {
                const double inv = 1.25 / ((double)NB * (double)ND);
                float tot = 0.f;
                for (int g2 = 0; g2 < NG; g2++) {
                    double a = 0.0;
                    for (int b = 0; b < XBLK; b++) a += (double)g_part[g2 * XBLK + b];
                    float pl = (float)(a * inv);
                    out_loss[g2] = pl;
                    tot += pl;
                }
                out_loss[NG] = tot;
            }
            g_done = 0;
        }
    }
}

extern "C" void kernel_launch(void* const* d_in, const int* in_sizes, int n_in,
                              void* d_out, int out_size) {
    const float* feat = (const float*)d_in[0];
    const float* cb   = (const float*)d_in[1];
    if (n_in >= 2 && in_sizes[0] == NG * NK * ND) {
        const float* t = feat; feat = cb; cb = t;
    }
    float* out = (float*)d_out;

    const long long q_elems   = (long long)NG * NB * ND;
    const long long idx_elems = (long long)NG * NB;
    const long long full_sz   = q_elems + NG + 1 + idx_elems;
    const int write_q    = ((long long)out_size >= q_elems);
    const int write_loss = ((long long)out_size >= q_elems + NG + 1);
    const int write_idx  = ((long long)out_size >= full_sz);

    const int smem_bytes = (ND * XPAD + ND * CPAD) * 8 + (NK + RB + 8) * 4;
    cudaFuncSetAttribute(vq_kernel,
                         cudaFuncAttributeMaxDynamicSharedMemorySize, smem_bytes);

    dim3 grid(XBLK, NG);
    float* out_loss = out + q_elems;
    float* out_idx  = out + q_elems + NG + 1;
    vq_kernel<<<grid, CTA, smem_bytes>>>(feat, cb, out, out_loss, out_idx,
                                         write_q, write_loss, write_idx);
}